// round 16
// baseline (speedup 1.0000x reference)
#include <cuda_runtime.h>
#include <cuda_bf16.h>
#include <cuda_fp16.h>
#include <math.h>
#include <cstdint>

// Problem constants
#define B_  2
#define T_  2048
#define D_  5120
#define HQ_ 32
#define HK_ 8
#define HD_ 160
#define RD_ 40
#define NTOK (B_ * T_)          // 4096
#define EPS_ 1e-5f
#define NQKV 7680               // 5120 + 1280 + 1280
#define KOFF 5120
#define VOFF 6400

// ---------------------------------------------------------------------------
// PTX helpers (generic sm_80+ subset)
// ---------------------------------------------------------------------------
__device__ __forceinline__ uint32_t smem_u32(const void* p) {
    uint32_t a;
    asm("{ .reg .u64 t; cvta.to.shared.u64 t, %1; cvt.u32.u64 %0, t; }" : "=r"(a) : "l"(p));
    return a;
}
__device__ __forceinline__ void cp16(uint32_t s, const void* g) {
    asm volatile("cp.async.cg.shared.global [%0], [%1], 16;" :: "r"(s), "l"(g));
}
#define CP_COMMIT() asm volatile("cp.async.commit_group;")
#define CP_WAIT0()  asm volatile("cp.async.wait_group 0;")
#define CP_WAIT1()  asm volatile("cp.async.wait_group 1;")
#define CP_WAIT2()  asm volatile("cp.async.wait_group 2;")

__device__ __forceinline__ void ldm4(uint32_t* r, uint32_t addr) {
    asm volatile("ldmatrix.sync.aligned.m8n8.x4.shared.b16 {%0,%1,%2,%3}, [%4];"
                 : "=r"(r[0]), "=r"(r[1]), "=r"(r[2]), "=r"(r[3]) : "r"(addr));
}
__device__ __forceinline__ void ldm4t(uint32_t* r, uint32_t addr) {
    asm volatile("ldmatrix.sync.aligned.m8n8.x4.trans.shared.b16 {%0,%1,%2,%3}, [%4];"
                 : "=r"(r[0]), "=r"(r[1]), "=r"(r[2]), "=r"(r[3]) : "r"(addr));
}
__device__ __forceinline__ void mma_f16(float* c, const uint32_t* a, const uint32_t* b) {
    asm volatile(
        "mma.sync.aligned.m16n8k16.row.col.f32.f16.f16.f32 "
        "{%0,%1,%2,%3}, {%4,%5,%6,%7}, {%8,%9}, {%0,%1,%2,%3};"
        : "+f"(c[0]), "+f"(c[1]), "+f"(c[2]), "+f"(c[3])
        : "r"(a[0]), "r"(a[1]), "r"(a[2]), "r"(a[3]), "r"(b[0]), "r"(b[1]));
}
// fast exp2 on the FMA pipe (|err| ~3e-6), input <= 0
__device__ __forceinline__ float exp2p(float x) {
    x = fmaxf(x, -80.f);
    float r = rintf(x);
    float f = x - r;
    float p = 1.33335581e-3f;
    p = fmaf(p, f, 9.61812910e-3f);
    p = fmaf(p, f, 5.55041087e-2f);
    p = fmaf(p, f, 2.40226507e-1f);
    p = fmaf(p, f, 6.93147180e-1f);
    p = fmaf(p, f, 1.0f);
    return p * __int_as_float(((int)r + 127) << 23);
}

// ---------------------------------------------------------------------------
// Scratch (device globals)
// ---------------------------------------------------------------------------
__device__ __half g_af[NTOK * D_];               // nx fp16
__device__ __half g_wtf[NQKV * D_];              // [wq|wk|wv]^T fp16 [7680,5120]
__device__ __half g_wof[D_ * D_];                // wo^T fp16 [5120,5120]
__device__ __half g_qkv[NTOK * NQKV];            // fused qkv output (fp16)
__device__ __half g_qf[NTOK * HQ_ * HD_];        // q head-major [B,HQ,T,HD] fp16
__device__ __half g_kf[NTOK * HK_ * HD_];        // k head-major [B,HK,T,HD] fp16
__device__ __half g_vf[NTOK * HK_ * HD_];        // v head-major fp16
__device__ __half g_of[NTOK * D_];               // attn out fp16 [tok, D]
__device__ float g_cos[T_ * RD_];
__device__ float g_sin[T_ * RD_];

// ---------------------------------------------------------------------------
// Kernel 0: RoPE tables (fp64)
// ---------------------------------------------------------------------------
__global__ void rope_table_kernel(float* __restrict__ tc, float* __restrict__ ts) {
    int idx = blockIdx.x * 256 + threadIdx.x;
    if (idx >= T_ * RD_) return;
    int t = idx / RD_;
    int i = idx % RD_;
    int f = i % 20;
    double invf = pow(5000000.0, -(double)f / 20.0);
    double ang = (double)t * invf;
    tc[idx] = (float)cos(ang);
    ts[idx] = (float)sin(ang);
}

// ---------------------------------------------------------------------------
// Kernel 1: weight transpose -> fp16, 3 sources fused (wq|wk|wv column blocks)
// ---------------------------------------------------------------------------
__global__ __launch_bounds__(256) void wsplit_h(
    const float* __restrict__ w0, const float* __restrict__ w1,
    const float* __restrict__ w2, __half* __restrict__ dst) {
    __shared__ float tile[32][33];
    int kb = blockIdx.y * 32, nb = blockIdx.x * 32;
    const float* src; int N; int nloc;
    if (nb < KOFF)      { src = w0; N = D_;        nloc = nb; }
    else if (nb < VOFF) { src = w1; N = HK_ * HD_; nloc = nb - KOFF; }
    else                { src = w2; N = HK_ * HD_; nloc = nb - VOFF; }
    int tx = threadIdx.x & 31, ty = threadIdx.x >> 5;
    #pragma unroll
    for (int i = 0; i < 4; i++)
        tile[ty + i * 8][tx] = src[(size_t)(kb + ty + i * 8) * N + nloc + tx];
    __syncthreads();
    #pragma unroll
    for (int i = 0; i < 4; i++) {
        int r = ty + i * 8;
        dst[(size_t)(nb + r) * D_ + kb + tx] = __float2half_rn(tile[tx][r]);
    }
}

// ---------------------------------------------------------------------------
// Kernel 2: RMS layernorm -> fp16, single pass over gmem (row cached in smem)
// ---------------------------------------------------------------------------
__global__ __launch_bounds__(256) void rmsnorm_kernel(
    const float* __restrict__ x, const float* __restrict__ w,
    const float* __restrict__ b, __half* __restrict__ o) {
    __shared__ float4 xs[D_ / 4];     // 20KB row cache
    int row = blockIdx.x;
    const float4* xr = (const float4*)(x + (size_t)row * D_);
    float ss = 0.f;
    #pragma unroll
    for (int i = threadIdx.x; i < D_ / 4; i += 256) {
        float4 v = xr[i];
        xs[i] = v;
        ss += v.x * v.x + v.y * v.y + v.z * v.z + v.w * v.w;
    }
    #pragma unroll
    for (int m = 16; m; m >>= 1) ss += __shfl_xor_sync(0xffffffffu, ss, m);
    __shared__ float red[8];
    if ((threadIdx.x & 31) == 0) red[threadIdx.x >> 5] = ss;
    __syncthreads();
    float tot = 0.f;
    #pragma unroll
    for (int i = 0; i < 8; i++) tot += red[i];
    float r = rsqrtf(tot * (1.0f / (float)D_) + EPS_);

    const float4* w4 = (const float4*)w;
    const float4* b4 = (const float4*)b;
    for (int i = threadIdx.x; i < D_ / 4; i += 256) {
        float4 v = xs[i], ww = w4[i], bb = b4[i];
        __half2 h01 = __floats2half2_rn(v.x * r * ww.x + bb.x, v.y * r * ww.y + bb.y);
        __half2 h23 = __floats2half2_rn(v.z * r * ww.z + bb.z, v.w * r * ww.w + bb.w);
        size_t base = (size_t)row * D_ + i * 4;
        *(__half2*)(o + base)     = h01;
        *(__half2*)(o + base + 2) = h23;
    }
}

// ---------------------------------------------------------------------------
// Kernel 3: fp16 HMMA GEMM (R10 proven). BM=128, BN=128, BK=64, 256 threads,
// 3-stage cp.async, 2 CTAs/SM. Templated output.
// ---------------------------------------------------------------------------
#define BM 128
#define BN 128
#define BK 64
#define PAD 72
#define ATILE (BM * PAD * 2)                 // 18432 B
#define BTILE (BN * PAD * 2)                 // 18432 B
#define STAGE (ATILE + BTILE)                // 36864 B
#define GEMM_SMEM (3 * STAGE)                // 110592 B

template <typename TO>
__global__ __launch_bounds__(256, 2) void hgemm(
    const __half* __restrict__ A, const __half* __restrict__ B,
    TO* __restrict__ C, int Kdim, int Nstride) {
    extern __shared__ char sm[];
    uint32_t smb = smem_u32(sm);
    const int tid = threadIdx.x;
    const int lane = tid & 31, wid = tid >> 5;
    const int wm = (wid >> 2) * 64;          // 0 or 64
    const int wn = (wid & 3) * 32;           // 0..96

    const size_t mBase = (size_t)blockIdx.y * BM;
    const size_t nBase = (size_t)blockIdx.x * BN;
    const __half* Ag = A + mBase * Kdim;
    const __half* Bg = B + nBase * Kdim;

    auto load = [&](int buf, int kc) {
        uint32_t base = smb + buf * STAGE;
        #pragma unroll
        for (int j = 0; j < 8; j++) {
            int c = tid + j * 256;              // 0..2047
            if (c < 1024) {
                int row = c >> 3, col = (c & 7) << 3;
                cp16(base + (row * PAD + col) * 2, Ag + (size_t)row * Kdim + kc + col);
            } else {
                int cc = c - 1024;
                int row = cc >> 3, col = (cc & 7) << 3;
                cp16(base + ATILE + (row * PAD + col) * 2, Bg + (size_t)row * Kdim + kc + col);
            }
        }
    };

    float acc[4][4][4];
    #pragma unroll
    for (int i = 0; i < 4; i++)
        #pragma unroll
        for (int j = 0; j < 4; j++)
            #pragma unroll
            for (int e = 0; e < 4; e++) acc[i][j][e] = 0.f;

    const int t8 = lane >> 3, r8 = lane & 7;
    const int aRow = wm + r8 + ((t8 & 1) << 3);
    const int aCol = (t8 >> 1) << 3;
    const int bRow = wn + r8 + ((t8 >> 1) << 3);
    const int bCol = (t8 & 1) << 3;

    const int KITERS = Kdim / BK;
    load(0, 0); CP_COMMIT();
    load(1, BK); CP_COMMIT();

    int buf = 0, pbuf = 2;       // current buffer, prefetch buffer (it+2)%3
    for (int it = 0; it < KITERS; ++it) {
        if (it + 1 < KITERS) { CP_WAIT1(); } else { CP_WAIT0(); }
        __syncthreads();

        uint32_t base = smb + buf * STAGE;
        uint32_t sA = base, sB = base + ATILE;

        #pragma unroll
        for (int ks = 0; ks < 4; ks++) {
            int k0 = ks << 4;
            uint32_t a[4][4];
            #pragma unroll
            for (int mf = 0; mf < 4; mf++)
                ldm4(a[mf], sA + ((aRow + mf * 16) * PAD + k0 + aCol) * 2);
            uint32_t b[4][2];
            #pragma unroll
            for (int nf2 = 0; nf2 < 2; nf2++) {
                uint32_t r[4];
                ldm4(r, sB + ((bRow + nf2 * 16) * PAD + k0 + bCol) * 2);
                b[nf2 * 2][0] = r[0]; b[nf2 * 2][1] = r[1];
                b[nf2 * 2 + 1][0] = r[2]; b[nf2 * 2 + 1][1] = r[3];
            }
            #pragma unroll
            for (int mf = 0; mf < 4; mf++)
                #pragma unroll
                for (int nf = 0; nf < 4; nf++)
                    mma_f16(acc[mf][nf], a[mf], b[nf]);
        }
        if (it + 2 < KITERS) {
            load(pbuf, (it + 2) * BK);
            CP_COMMIT();
        }
        buf = (buf == 2) ? 0 : buf + 1;
        pbuf = (pbuf == 2) ? 0 : pbuf + 1;
    }

    TO* Cb = C + (mBase + wm) * Nstride + nBase + wn;
    const int er = lane >> 2, ec = (lane & 3) * 2;
    #pragma unroll
    for (int mf = 0; mf < 4; mf++) {
        #pragma unroll
        for (int nf = 0; nf < 4; nf++) {
            TO* p0 = Cb + (size_t)(mf * 16 + er) * Nstride + nf * 8 + ec;
            TO* p1 = p0 + 8 * (size_t)Nstride;
            if constexpr (sizeof(TO) == 2) {
                __half2 v0 = __floats2half2_rn(acc[mf][nf][0], acc[mf][nf][1]);
                __half2 v1 = __floats2half2_rn(acc[mf][nf][2], acc[mf][nf][3]);
                *(__half2*)p0 = v0;
                *(__half2*)p1 = v1;
            } else {
                p0[0] = acc[mf][nf][0];
                p0[1] = acc[mf][nf][1];
                p1[0] = acc[mf][nf][2];
                p1[1] = acc[mf][nf][3];
            }
        }
    }
}

// ---------------------------------------------------------------------------
// Kernel 4: merged head prep (q, k, v in one launch; block-range dispatch).
// Per-head RMS + partial RoPE (q, k) or plain copy (v) -> fp16 head-major.
// One warp per (token, head) row.
// ---------------------------------------------------------------------------
#define QP_BLKS ((NTOK * HQ_) / 8)       // 16384
#define KP_BLKS ((NTOK * HK_) / 8)       // 4096
#define HP_BLKS (QP_BLKS + 2 * KP_BLKS)  // 24576

__global__ __launch_bounds__(256) void head_prep_all(
    const __half* __restrict__ qkv, const float* __restrict__ qn_w,
    const float* __restrict__ kn_w, const float* __restrict__ tcos,
    const float* __restrict__ tsin, __half* __restrict__ qf,
    __half* __restrict__ kf, __half* __restrict__ vf) {
    int blk = blockIdx.x;
    int H, src_off, do_norm;
    const float* w;
    __half* dst;
    if (blk < QP_BLKS) {
        H = HQ_; src_off = 0; do_norm = 1; w = qn_w; dst = qf;
    } else if (blk < QP_BLKS + KP_BLKS) {
        blk -= QP_BLKS;
        H = HK_; src_off = KOFF; do_norm = 1; w = kn_w; dst = kf;
    } else {
        blk -= QP_BLKS + KP_BLKS;
        H = HK_; src_off = VOFF; do_norm = 0; w = kn_w; dst = vf;
    }
    int rowi = blk * 8 + (threadIdx.x >> 5);
    int lane = threadIdx.x & 31;
    int h = rowi % H;
    int tok = rowi / H;
    int t = tok & (T_ - 1);
    int b = tok >> 11;

    const __half* p = qkv + (size_t)tok * NQKV + src_off + h * HD_;
    float v[5];
    #pragma unroll
    for (int i = 0; i < 5; i++) v[i] = __half2float(p[lane + 32 * i]);

    if (do_norm) {
        float ss = 0.f;
        #pragma unroll
        for (int i = 0; i < 5; i++) ss += v[i] * v[i];
        #pragma unroll
        for (int m = 16; m; m >>= 1) ss += __shfl_xor_sync(0xffffffffu, ss, m);
        float r = rsqrtf(ss * (1.0f / (float)HD_) + EPS_);
        const float* wh = w + h * HD_;
        #pragma unroll
        for (int i = 0; i < 5; i++) v[i] *= r * wh[lane + 32 * i];
        {   // RoPE d = lane (0..31)
            float partner = __shfl_xor_sync(0xffffffffu, v[0], 1);
            float rot = (lane & 1) ? partner : -partner;
            v[0] = v[0] * tcos[t * RD_ + lane] + rot * tsin[t * RD_ + lane];
        }
        {   // RoPE d = 32..39
            float partner = __shfl_xor_sync(0xffffffffu, v[1], 1);
            if (lane < 8) {
                int d = 32 + lane;
                float rot = (lane & 1) ? partner : -partner;
                v[1] = v[1] * tcos[t * RD_ + d] + rot * tsin[t * RD_ + d];
            }
        }
    }
    size_t dbase = ((size_t)(b * H + h) * T_ + t) * HD_;
    #pragma unroll
    for (int i = 0; i < 5; i++)
        dst[dbase + lane + 32 * i] = __float2half_rn(v[i]);
}

// ---------------------------------------------------------------------------
// Kernel 5: fp16 HMMA causal flash attention (R15 proven, best measured).
// BQ=128, BKV=128, 256 thr, K/V double-buffered, online softmax,
// l-reduction deferred to epilogue.
// ---------------------------------------------------------------------------
#define ROWB 336                    // 168 halves * 2 bytes
#define FQ_SZ 43008                 // 128 * ROWB
#define FKV_SZ 43008                // 128 * ROWB
#define FKOFF FQ_SZ                 // K bufs (x2)
#define FVOFF (FQ_SZ + 2 * FKV_SZ)  // V bufs (x2)
#define FLASH_SMEM (FQ_SZ + 4 * FKV_SZ)   // 215040

__global__ __launch_bounds__(256, 1) void flash_hmma(
    const __half* __restrict__ Qf, const __half* __restrict__ Kf,
    const __half* __restrict__ Vf, __half* __restrict__ Of) {
    extern __shared__ char sm[];
    uint32_t smb = smem_u32(sm);
    const int qt = (T_ / 128 - 1) - blockIdx.x;   // heavy tiles first
    const int h = blockIdx.y, b = blockIdx.z;
    const int hk = h >> 2;
    const int tid = threadIdx.x, lane = tid & 31, wid = tid >> 5;

    const __half* Qg = Qf + ((size_t)(b * HQ_ + h) * T_ + qt * 128) * HD_;
    const __half* Kg = Kf + (size_t)(b * HK_ + hk) * T_ * HD_;
    const __half* Vg = Vf + (size_t)(b * HK_ + hk) * T_ * HD_;

    #pragma unroll
    for (int j = 0; j < 10; j++) {
        int c = tid + j * 256;
        int row = c / 20, col = (c % 20) * 8;
        cp16(smb + row * ROWB + col * 2, Qg + row * HD_ + col);
    }
    auto load_k = [&](int buf, int kt) {
        uint32_t base = smb + FKOFF + buf * FKV_SZ;
        const __half* s = Kg + (size_t)kt * 128 * HD_;
        #pragma unroll
        for (int j = 0; j < 10; j++) {
            int c = tid + j * 256;
            int row = c / 20, col = (c % 20) * 8;
            cp16(base + row * ROWB + col * 2, s + row * HD_ + col);
        }
    };
    auto load_v = [&](int buf, int kt) {
        uint32_t base = smb + FVOFF + buf * FKV_SZ;
        const __half* s = Vg + (size_t)kt * 128 * HD_;
        #pragma unroll
        for (int j = 0; j < 10; j++) {
            int c = tid + j * 256;
            int row = c / 20, col = (c % 20) * 8;
            cp16(base + row * ROWB + col * 2, s + row * HD_ + col);
        }
    };

    load_k(0, 0); CP_COMMIT();      // group: Q + K0
    load_v(0, 0); CP_COMMIT();      // group: V0

    float m0 = -1e30f, m1 = -1e30f, l0 = 0.f, l1 = 0.f;
    float o[20][4];
    #pragma unroll
    for (int f = 0; f < 20; f++)
        #pragma unroll
        for (int e = 0; e < 4; e++) o[f][e] = 0.f;

    const int gr = lane >> 2, ct = lane & 3;
    const int ldrow = (lane & 7) + ((lane >> 3) & 1) * 8;
    const int ldcol = ((lane >> 4) & 1) * 8;
    const uint32_t q_b = smb + (wid * 16 + ldrow) * ROWB + ldcol * 2;
    const int rowg0 = qt * 128 + wid * 16 + gr;

    const int nkt = qt + 1;
    const float sc = 0.07905694150420949f * 1.4426950408889634f;  // scale*log2e

    for (int kt = 0; kt < nkt; kt++) {
        if (kt + 1 < nkt) {
            load_k((kt + 1) & 1, kt + 1); CP_COMMIT();
            load_v((kt + 1) & 1, kt + 1); CP_COMMIT();
            CP_WAIT2();
        } else {
            CP_WAIT0();
        }
        __syncthreads();

        // ---- S = Q K^T (128 kv cols: 16 n8-fragments) ----
        float s[16][4];
        #pragma unroll
        for (int f = 0; f < 16; f++)
            #pragma unroll
            for (int e = 0; e < 4; e++) s[f][e] = 0.f;

        uint32_t kb = smb + FKOFF + (kt & 1) * FKV_SZ + ldrow * ROWB + ldcol * 2;
        #pragma unroll
        for (int ks = 0; ks < 10; ks++) {
            uint32_t a[4];
            ldm4(a, q_b + ks * 32);
            #pragma unroll
            for (int ng = 0; ng < 8; ng++) {
                uint32_t r[4];
                ldm4(r, kb + ng * 16 * ROWB + ks * 32);
                uint32_t b0[2] = {r[0], r[2]}, b1[2] = {r[1], r[3]};
                mma_f16(s[2 * ng], a, b0);
                mma_f16(s[2 * ng + 1], a, b1);
            }
        }

        // ---- mask + scale (base-2 domain) ----
        if (kt == nkt - 1) {     // diagonal tile
            #pragma unroll
            for (int f = 0; f < 16; f++) {
                int col = kt * 128 + f * 8 + 2 * ct;
                s[f][0] = (col     > rowg0)     ? -1e30f : s[f][0] * sc;
                s[f][1] = (col + 1 > rowg0)     ? -1e30f : s[f][1] * sc;
                s[f][2] = (col     > rowg0 + 8) ? -1e30f : s[f][2] * sc;
                s[f][3] = (col + 1 > rowg0 + 8) ? -1e30f : s[f][3] * sc;
            }
        } else {
            #pragma unroll
            for (int f = 0; f < 16; f++)
                #pragma unroll
                for (int e = 0; e < 4; e++) s[f][e] *= sc;
        }

        // ---- online softmax (max reduced across quad; l kept per-thread) ----
        float r0 = -1e30f, r1 = -1e30f;
        #pragma unroll
        for (int f = 0; f < 16; f++) {
            r0 = fmaxf(r0, fmaxf(s[f][0], s[f][1]));
            r1 = fmaxf(r1, fmaxf(s[f][2], s[f][3]));
        }
        r0 = fmaxf(r0, __shfl_xor_sync(0xffffffffu, r0, 1));
        r0 = fmaxf(r0, __shfl_xor_sync(0xffffffffu, r0, 2));
        r1 = fmaxf(r1, __shfl_xor_sync(0xffffffffu, r1, 1));
        r1 = fmaxf(r1, __shfl_xor_sync(0xffffffffu, r1, 2));
        float mn0 = fmaxf(m0, r0), mn1 = fmaxf(m1, r1);
        float a0 = exp2p(m0 - mn0), a1 = exp2p(m1 - mn1);
        m0 = mn0; m1 = mn1;

        float rs0 = 0.f, rs1 = 0.f;
        uint32_t pA[16], pB[16];
        #pragma unroll
        for (int f = 0; f < 16; f++) {
            float p0 = exp2p(s[f][0] - mn0);
            float p1 = exp2p(s[f][1] - mn0);
            float p2 = exp2p(s[f][2] - mn1);
            float p3 = exp2p(s[f][3] - mn1);
            rs0 += p0 + p1; rs1 += p2 + p3;
            __half2 hA = __floats2half2_rn(p0, p1);
            __half2 hB = __floats2half2_rn(p2, p3);
            pA[f] = *(uint32_t*)&hA;
            pB[f] = *(uint32_t*)&hB;
        }
        l0 = l0 * a0 + rs0;
        l1 = l1 * a1 + rs1;
        #pragma unroll
        for (int f = 0; f < 20; f++) {
            o[f][0] *= a0; o[f][1] *= a0; o[f][2] *= a1; o[f][3] *= a1;
        }

        // ---- O += P V (128 kv rows: 8 k16 chunks) ----
        uint32_t vbase = smb + FVOFF + (kt & 1) * FKV_SZ;
        #pragma unroll
        for (int ks = 0; ks < 8; ks++) {
            uint32_t a[4] = {pA[2 * ks], pB[2 * ks], pA[2 * ks + 1], pB[2 * ks + 1]};
            uint32_t vb = vbase + (ks * 16 + ldrow) * ROWB + ldcol * 2;
            #pragma unroll
            for (int nb = 0; nb < 10; nb++) {
                uint32_t r[4];
                ldm4t(r, vb + nb * 32);
                uint32_t b0[2] = {r[0], r[1]}, b1[2] = {r[2], r[3]};
                mma_f16(o[2 * nb], a, b0);
                mma_f16(o[2 * nb + 1], a, b1);
            }
        }
        __syncthreads();
    }

    // ---- epilogue: one l reduction, normalize, write fp16 [tok][D] ----
    l0 += __shfl_xor_sync(0xffffffffu, l0, 1);
    l0 += __shfl_xor_sync(0xffffffffu, l0, 2);
    l1 += __shfl_xor_sync(0xffffffffu, l1, 1);
    l1 += __shfl_xor_sync(0xffffffffu, l1, 2);
    float i0 = 1.f / l0, i1 = 1.f / l1;
    size_t rb0 = (size_t)(b * T_ + qt * 128 + wid * 16 + gr) * D_ + h * HD_;
    size_t rb1 = rb0 + 8 * (size_t)D_;
    #pragma unroll
    for (int f = 0; f < 20; f++) {
        int col = f * 8 + 2 * ct;
        __half2 h01 = __floats2half2_rn(o[f][0] * i0, o[f][1] * i0);
        __half2 h23 = __floats2half2_rn(o[f][2] * i1, o[f][3] * i1);
        *(uint32_t*)(Of + rb0 + col) = *(uint32_t*)&h01;
        *(uint32_t*)(Of + rb1 + col) = *(uint32_t*)&h23;
    }
}

// ---------------------------------------------------------------------------
// Host launch: weight transposes forked onto a second stream so they run
// concurrently with rmsnorm / the QKV GEMM (event fork/join, capturable).
// ---------------------------------------------------------------------------
extern "C" void kernel_launch(void* const* d_in, const int* in_sizes, int n_in,
                              void* d_out, int out_size) {
    const float* x      = (const float*)d_in[0];
    const float* wq     = (const float*)d_in[1];
    const float* wk     = (const float*)d_in[2];
    const float* wv     = (const float*)d_in[3];
    const float* wo     = (const float*)d_in[4];
    const float* norm_w = (const float*)d_in[5];
    const float* norm_b = (const float*)d_in[6];
    const float* qn_w   = (const float*)d_in[7];
    const float* kn_w   = (const float*)d_in[8];
    float* out = (float*)d_out;

    __half *af, *wtf, *wof, *of, *qf, *kf, *vf, *qkv;
    float *tcos, *tsin;
    cudaGetSymbolAddress((void**)&af,   g_af);
    cudaGetSymbolAddress((void**)&wtf,  g_wtf);
    cudaGetSymbolAddress((void**)&wof,  g_wof);
    cudaGetSymbolAddress((void**)&of,   g_of);
    cudaGetSymbolAddress((void**)&qf,   g_qf);
    cudaGetSymbolAddress((void**)&kf,   g_kf);
    cudaGetSymbolAddress((void**)&vf,   g_vf);
    cudaGetSymbolAddress((void**)&qkv,  g_qkv);
    cudaGetSymbolAddress((void**)&tcos, g_cos);
    cudaGetSymbolAddress((void**)&tsin, g_sin);

    cudaFuncSetAttribute(hgemm<__half>, cudaFuncAttributeMaxDynamicSharedMemorySize, GEMM_SMEM);
    cudaFuncSetAttribute(hgemm<float>,  cudaFuncAttributeMaxDynamicSharedMemorySize, GEMM_SMEM);
    cudaFuncSetAttribute(flash_hmma, cudaFuncAttributeMaxDynamicSharedMemorySize, FLASH_SMEM);

    // Side stream + events (host handles only; leaked -- kernel_launch is
    // invoked a bounded number of times, and destroy-during-capture is UB).
    cudaStream_t s2;
    cudaEvent_t evFork, evA, evJoin;
    cudaStreamCreateWithFlags(&s2, cudaStreamNonBlocking);
    cudaEventCreateWithFlags(&evFork, cudaEventDisableTiming);
    cudaEventCreateWithFlags(&evA,    cudaEventDisableTiming);
    cudaEventCreateWithFlags(&evJoin, cudaEventDisableTiming);

    // fork
    cudaEventRecord(evFork, 0);
    cudaStreamWaitEvent(s2, evFork, 0);

    // s2: qkv weight transpose + rope tables (needed before QKV GEMM / prep)
    wsplit_h<<<dim3(NQKV / 32, D_ / 32), 256, 0, s2>>>(wq, wk, wv, wtf);
    rope_table_kernel<<<(T_ * RD_ + 255) / 256, 256, 0, s2>>>(tcos, tsin);
    cudaEventRecord(evA, s2);
    // s2 continues: wo transpose (only needed before the final GEMM)
    wsplit_h<<<dim3(D_ / 32, D_ / 32), 256, 0, s2>>>(wo, wo, wo, wof);
    cudaEventRecord(evJoin, s2);

    // main: RMS layernorm concurrently with s2's transposes
    rmsnorm_kernel<<<NTOK, 256>>>(x, norm_w, norm_b, af);

    // main waits for wtf + rope tables
    cudaStreamWaitEvent(0, evA, 0);
    // QKV projection (wo transpose overlaps with this on s2)
    hgemm<__half><<<dim3(NQKV / BN, NTOK / BM), 256, GEMM_SMEM>>>(af, wtf, qkv, D_, NQKV);
    // merged head prep (q norm+rope, k norm+rope, v copy)
    head_prep_all<<<HP_BLKS, 256>>>(qkv, qn_w, kn_w, tcos, tsin, qf, kf, vf);
    // flash attention
    flash_hmma<<<dim3(T_ / 128, HQ_, B_), 256, FLASH_SMEM>>>(qf, kf, vf, of);
    // join: wo transpose must be done before the output projection
    cudaStreamWaitEvent(0, evJoin, 0);
    hgemm<float><<<dim3(D_ / BN, NTOK / BM), 256, GEMM_SMEM>>>(of, wof, out, D_, D_);
}

// round 17
// speedup vs baseline: 1.0051x; 1.0051x over previous
#include <cuda_runtime.h>
#include <cuda_bf16.h>
#include <cuda_fp16.h>
#include <math.h>
#include <cstdint>

// Problem constants
#define B_  2
#define T_  2048
#define D_  5120
#define HQ_ 32
#define HK_ 8
#define HD_ 160
#define RD_ 40
#define NTOK (B_ * T_)          // 4096
#define EPS_ 1e-5f
#define NQKV 7680               // 5120 + 1280 + 1280
#define KOFF 5120
#define VOFF 6400

// ---------------------------------------------------------------------------
// PTX helpers (generic sm_80+ subset)
// ---------------------------------------------------------------------------
__device__ __forceinline__ uint32_t smem_u32(const void* p) {
    uint32_t a;
    asm("{ .reg .u64 t; cvta.to.shared.u64 t, %1; cvt.u32.u64 %0, t; }" : "=r"(a) : "l"(p));
    return a;
}
__device__ __forceinline__ void cp16(uint32_t s, const void* g) {
    asm volatile("cp.async.cg.shared.global [%0], [%1], 16;" :: "r"(s), "l"(g));
}
#define CP_COMMIT() asm volatile("cp.async.commit_group;")
#define CP_WAIT0()  asm volatile("cp.async.wait_group 0;")
#define CP_WAIT1()  asm volatile("cp.async.wait_group 1;")
#define CP_WAIT2()  asm volatile("cp.async.wait_group 2;")

__device__ __forceinline__ void ldm4(uint32_t* r, uint32_t addr) {
    asm volatile("ldmatrix.sync.aligned.m8n8.x4.shared.b16 {%0,%1,%2,%3}, [%4];"
                 : "=r"(r[0]), "=r"(r[1]), "=r"(r[2]), "=r"(r[3]) : "r"(addr));
}
__device__ __forceinline__ void ldm4t(uint32_t* r, uint32_t addr) {
    asm volatile("ldmatrix.sync.aligned.m8n8.x4.trans.shared.b16 {%0,%1,%2,%3}, [%4];"
                 : "=r"(r[0]), "=r"(r[1]), "=r"(r[2]), "=r"(r[3]) : "r"(addr));
}
__device__ __forceinline__ void mma_f16(float* c, const uint32_t* a, const uint32_t* b) {
    asm volatile(
        "mma.sync.aligned.m16n8k16.row.col.f32.f16.f16.f32 "
        "{%0,%1,%2,%3}, {%4,%5,%6,%7}, {%8,%9}, {%0,%1,%2,%3};"
        : "+f"(c[0]), "+f"(c[1]), "+f"(c[2]), "+f"(c[3])
        : "r"(a[0]), "r"(a[1]), "r"(a[2]), "r"(a[3]), "r"(b[0]), "r"(b[1]));
}
// fast exp2 on the FMA pipe (|err| ~3e-6), input <= 0
__device__ __forceinline__ float exp2p(float x) {
    x = fmaxf(x, -80.f);
    float r = rintf(x);
    float f = x - r;
    float p = 1.33335581e-3f;
    p = fmaf(p, f, 9.61812910e-3f);
    p = fmaf(p, f, 5.55041087e-2f);
    p = fmaf(p, f, 2.40226507e-1f);
    p = fmaf(p, f, 6.93147180e-1f);
    p = fmaf(p, f, 1.0f);
    return p * __int_as_float(((int)r + 127) << 23);
}

// ---------------------------------------------------------------------------
// Scratch (device globals)
// ---------------------------------------------------------------------------
__device__ __half g_af[NTOK * D_];               // nx fp16
__device__ __half g_wtf[NQKV * D_];              // [wq|wk|wv]^T fp16 [7680,5120]
__device__ __half g_wof[D_ * D_];                // wo^T fp16 [5120,5120]
__device__ __half g_qkv[NTOK * NQKV];            // fused qkv output (fp16)
__device__ __half g_qf[NTOK * HQ_ * HD_];        // q head-major [B,HQ,T,HD] fp16
__device__ __half g_kf[NTOK * HK_ * HD_];        // k head-major [B,HK,T,HD] fp16
__device__ __half g_vf[NTOK * HK_ * HD_];        // v head-major fp16
__device__ __half g_of[NTOK * D_];               // attn out fp16 [tok, D]
__device__ float g_cos[T_ * RD_];
__device__ float g_sin[T_ * RD_];

// ---------------------------------------------------------------------------
// Kernel 0: RoPE tables (fp64)
// ---------------------------------------------------------------------------
__global__ void rope_table_kernel(float* __restrict__ tc, float* __restrict__ ts) {
    int idx = blockIdx.x * 256 + threadIdx.x;
    if (idx >= T_ * RD_) return;
    int t = idx / RD_;
    int i = idx % RD_;
    int f = i % 20;
    double invf = pow(5000000.0, -(double)f / 20.0);
    double ang = (double)t * invf;
    tc[idx] = (float)cos(ang);
    ts[idx] = (float)sin(ang);
}

// ---------------------------------------------------------------------------
// Kernel 1: weight transpose -> fp16, 3 sources fused (wq|wk|wv column blocks)
// ---------------------------------------------------------------------------
__global__ __launch_bounds__(256) void wsplit_h(
    const float* __restrict__ w0, const float* __restrict__ w1,
    const float* __restrict__ w2, __half* __restrict__ dst) {
    __shared__ float tile[32][33];
    int kb = blockIdx.y * 32, nb = blockIdx.x * 32;
    const float* src; int N; int nloc;
    if (nb < KOFF)      { src = w0; N = D_;        nloc = nb; }
    else if (nb < VOFF) { src = w1; N = HK_ * HD_; nloc = nb - KOFF; }
    else                { src = w2; N = HK_ * HD_; nloc = nb - VOFF; }
    int tx = threadIdx.x & 31, ty = threadIdx.x >> 5;
    #pragma unroll
    for (int i = 0; i < 4; i++)
        tile[ty + i * 8][tx] = src[(size_t)(kb + ty + i * 8) * N + nloc + tx];
    __syncthreads();
    #pragma unroll
    for (int i = 0; i < 4; i++) {
        int r = ty + i * 8;
        dst[(size_t)(nb + r) * D_ + kb + tx] = __float2half_rn(tile[tx][r]);
    }
}

// ---------------------------------------------------------------------------
// Kernel 2: RMS layernorm -> fp16, single pass over gmem (row cached in smem)
// ---------------------------------------------------------------------------
__global__ __launch_bounds__(256) void rmsnorm_kernel(
    const float* __restrict__ x, const float* __restrict__ w,
    const float* __restrict__ b, __half* __restrict__ o) {
    __shared__ float4 xs[D_ / 4];     // 20KB row cache
    int row = blockIdx.x;
    const float4* xr = (const float4*)(x + (size_t)row * D_);
    float ss = 0.f;
    #pragma unroll
    for (int i = threadIdx.x; i < D_ / 4; i += 256) {
        float4 v = xr[i];
        xs[i] = v;
        ss += v.x * v.x + v.y * v.y + v.z * v.z + v.w * v.w;
    }
    #pragma unroll
    for (int m = 16; m; m >>= 1) ss += __shfl_xor_sync(0xffffffffu, ss, m);
    __shared__ float red[8];
    if ((threadIdx.x & 31) == 0) red[threadIdx.x >> 5] = ss;
    __syncthreads();
    float tot = 0.f;
    #pragma unroll
    for (int i = 0; i < 8; i++) tot += red[i];
    float r = rsqrtf(tot * (1.0f / (float)D_) + EPS_);

    const float4* w4 = (const float4*)w;
    const float4* b4 = (const float4*)b;
    for (int i = threadIdx.x; i < D_ / 4; i += 256) {
        float4 v = xs[i], ww = w4[i], bb = b4[i];
        __half2 h01 = __floats2half2_rn(v.x * r * ww.x + bb.x, v.y * r * ww.y + bb.y);
        __half2 h23 = __floats2half2_rn(v.z * r * ww.z + bb.z, v.w * r * ww.w + bb.w);
        size_t base = (size_t)row * D_ + i * 4;
        *(__half2*)(o + base)     = h01;
        *(__half2*)(o + base + 2) = h23;
    }
}

// ---------------------------------------------------------------------------
// Kernel 3: fp16 HMMA GEMM (R10 proven). BM=128, BN=128, BK=64, 256 threads,
// 3-stage cp.async, 2 CTAs/SM. Templated output.
// ---------------------------------------------------------------------------
#define BM 128
#define BN 128
#define BK 64
#define PAD 72
#define ATILE (BM * PAD * 2)                 // 18432 B
#define BTILE (BN * PAD * 2)                 // 18432 B
#define STAGE (ATILE + BTILE)                // 36864 B
#define GEMM_SMEM (3 * STAGE)                // 110592 B

template <typename TO>
__global__ __launch_bounds__(256, 2) void hgemm(
    const __half* __restrict__ A, const __half* __restrict__ B,
    TO* __restrict__ C, int Kdim, int Nstride) {
    extern __shared__ char sm[];
    uint32_t smb = smem_u32(sm);
    const int tid = threadIdx.x;
    const int lane = tid & 31, wid = tid >> 5;
    const int wm = (wid >> 2) * 64;          // 0 or 64
    const int wn = (wid & 3) * 32;           // 0..96

    const size_t mBase = (size_t)blockIdx.y * BM;
    const size_t nBase = (size_t)blockIdx.x * BN;
    const __half* Ag = A + mBase * Kdim;
    const __half* Bg = B + nBase * Kdim;

    auto load = [&](int buf, int kc) {
        uint32_t base = smb + buf * STAGE;
        #pragma unroll
        for (int j = 0; j < 8; j++) {
            int c = tid + j * 256;              // 0..2047
            if (c < 1024) {
                int row = c >> 3, col = (c & 7) << 3;
                cp16(base + (row * PAD + col) * 2, Ag + (size_t)row * Kdim + kc + col);
            } else {
                int cc = c - 1024;
                int row = cc >> 3, col = (cc & 7) << 3;
                cp16(base + ATILE + (row * PAD + col) * 2, Bg + (size_t)row * Kdim + kc + col);
            }
        }
    };

    float acc[4][4][4];
    #pragma unroll
    for (int i = 0; i < 4; i++)
        #pragma unroll
        for (int j = 0; j < 4; j++)
            #pragma unroll
            for (int e = 0; e < 4; e++) acc[i][j][e] = 0.f;

    const int t8 = lane >> 3, r8 = lane & 7;
    const int aRow = wm + r8 + ((t8 & 1) << 3);
    const int aCol = (t8 >> 1) << 3;
    const int bRow = wn + r8 + ((t8 >> 1) << 3);
    const int bCol = (t8 & 1) << 3;

    const int KITERS = Kdim / BK;
    load(0, 0); CP_COMMIT();
    load(1, BK); CP_COMMIT();

    int buf = 0, pbuf = 2;       // current buffer, prefetch buffer (it+2)%3
    for (int it = 0; it < KITERS; ++it) {
        if (it + 1 < KITERS) { CP_WAIT1(); } else { CP_WAIT0(); }
        __syncthreads();

        uint32_t base = smb + buf * STAGE;
        uint32_t sA = base, sB = base + ATILE;

        #pragma unroll
        for (int ks = 0; ks < 4; ks++) {
            int k0 = ks << 4;
            uint32_t a[4][4];
            #pragma unroll
            for (int mf = 0; mf < 4; mf++)
                ldm4(a[mf], sA + ((aRow + mf * 16) * PAD + k0 + aCol) * 2);
            uint32_t b[4][2];
            #pragma unroll
            for (int nf2 = 0; nf2 < 2; nf2++) {
                uint32_t r[4];
                ldm4(r, sB + ((bRow + nf2 * 16) * PAD + k0 + bCol) * 2);
                b[nf2 * 2][0] = r[0]; b[nf2 * 2][1] = r[1];
                b[nf2 * 2 + 1][0] = r[2]; b[nf2 * 2 + 1][1] = r[3];
            }
            #pragma unroll
            for (int mf = 0; mf < 4; mf++)
                #pragma unroll
                for (int nf = 0; nf < 4; nf++)
                    mma_f16(acc[mf][nf], a[mf], b[nf]);
        }
        if (it + 2 < KITERS) {
            load(pbuf, (it + 2) * BK);
            CP_COMMIT();
        }
        buf = (buf == 2) ? 0 : buf + 1;
        pbuf = (pbuf == 2) ? 0 : pbuf + 1;
    }

    TO* Cb = C + (mBase + wm) * Nstride + nBase + wn;
    const int er = lane >> 2, ec = (lane & 3) * 2;
    #pragma unroll
    for (int mf = 0; mf < 4; mf++) {
        #pragma unroll
        for (int nf = 0; nf < 4; nf++) {
            TO* p0 = Cb + (size_t)(mf * 16 + er) * Nstride + nf * 8 + ec;
            TO* p1 = p0 + 8 * (size_t)Nstride;
            if constexpr (sizeof(TO) == 2) {
                __half2 v0 = __floats2half2_rn(acc[mf][nf][0], acc[mf][nf][1]);
                __half2 v1 = __floats2half2_rn(acc[mf][nf][2], acc[mf][nf][3]);
                *(__half2*)p0 = v0;
                *(__half2*)p1 = v1;
            } else {
                p0[0] = acc[mf][nf][0];
                p0[1] = acc[mf][nf][1];
                p1[0] = acc[mf][nf][2];
                p1[1] = acc[mf][nf][3];
            }
        }
    }
}

// ---------------------------------------------------------------------------
// Kernel 4: merged head prep (q, k, v in one launch; block-range dispatch).
// Per-head RMS + partial RoPE (q, k) or plain copy (v) -> fp16 head-major.
// One warp per (token, head) row.
// ---------------------------------------------------------------------------
#define QP_BLKS ((NTOK * HQ_) / 8)       // 16384
#define KP_BLKS ((NTOK * HK_) / 8)       // 4096
#define HP_BLKS (QP_BLKS + 2 * KP_BLKS)  // 24576

__global__ __launch_bounds__(256) void head_prep_all(
    const __half* __restrict__ qkv, const float* __restrict__ qn_w,
    const float* __restrict__ kn_w, const float* __restrict__ tcos,
    const float* __restrict__ tsin, __half* __restrict__ qf,
    __half* __restrict__ kf, __half* __restrict__ vf) {
    int blk = blockIdx.x;
    int H, src_off, do_norm;
    const float* w;
    __half* dst;
    if (blk < QP_BLKS) {
        H = HQ_; src_off = 0; do_norm = 1; w = qn_w; dst = qf;
    } else if (blk < QP_BLKS + KP_BLKS) {
        blk -= QP_BLKS;
        H = HK_; src_off = KOFF; do_norm = 1; w = kn_w; dst = kf;
    } else {
        blk -= QP_BLKS + KP_BLKS;
        H = HK_; src_off = VOFF; do_norm = 0; w = kn_w; dst = vf;
    }
    int rowi = blk * 8 + (threadIdx.x >> 5);
    int lane = threadIdx.x & 31;
    int h = rowi % H;
    int tok = rowi / H;
    int t = tok & (T_ - 1);
    int b = tok >> 11;

    const __half* p = qkv + (size_t)tok * NQKV + src_off + h * HD_;
    float v[5];
    #pragma unroll
    for (int i = 0; i < 5; i++) v[i] = __half2float(p[lane + 32 * i]);

    if (do_norm) {
        float ss = 0.f;
        #pragma unroll
        for (int i = 0; i < 5; i++) ss += v[i] * v[i];
        #pragma unroll
        for (int m = 16; m; m >>= 1) ss += __shfl_xor_sync(0xffffffffu, ss, m);
        float r = rsqrtf(ss * (1.0f / (float)HD_) + EPS_);
        const float* wh = w + h * HD_;
        #pragma unroll
        for (int i = 0; i < 5; i++) v[i] *= r * wh[lane + 32 * i];
        {   // RoPE d = lane (0..31)
            float partner = __shfl_xor_sync(0xffffffffu, v[0], 1);
            float rot = (lane & 1) ? partner : -partner;
            v[0] = v[0] * tcos[t * RD_ + lane] + rot * tsin[t * RD_ + lane];
        }
        {   // RoPE d = 32..39
            float partner = __shfl_xor_sync(0xffffffffu, v[1], 1);
            if (lane < 8) {
                int d = 32 + lane;
                float rot = (lane & 1) ? partner : -partner;
                v[1] = v[1] * tcos[t * RD_ + d] + rot * tsin[t * RD_ + d];
            }
        }
    }
    size_t dbase = ((size_t)(b * H + h) * T_ + t) * HD_;
    #pragma unroll
    for (int i = 0; i < 5; i++)
        dst[dbase + lane + 32 * i] = __float2half_rn(v[i]);
}

// ---------------------------------------------------------------------------
// Kernel 5: fp16 HMMA causal flash attention (R15 proven, best measured).
// BQ=128, BKV=128, 256 thr, K/V double-buffered, online softmax,
// l-reduction deferred to epilogue.
// ---------------------------------------------------------------------------
#define ROWB 336                    // 168 halves * 2 bytes
#define FQ_SZ 43008                 // 128 * ROWB
#define FKV_SZ 43008                // 128 * ROWB
#define FKOFF FQ_SZ                 // K bufs (x2)
#define FVOFF (FQ_SZ + 2 * FKV_SZ)  // V bufs (x2)
#define FLASH_SMEM (FQ_SZ + 4 * FKV_SZ)   // 215040

__global__ __launch_bounds__(256, 1) void flash_hmma(
    const __half* __restrict__ Qf, const __half* __restrict__ Kf,
    const __half* __restrict__ Vf, __half* __restrict__ Of) {
    extern __shared__ char sm[];
    uint32_t smb = smem_u32(sm);
    const int qt = (T_ / 128 - 1) - blockIdx.x;   // heavy tiles first
    const int h = blockIdx.y, b = blockIdx.z;
    const int hk = h >> 2;
    const int tid = threadIdx.x, lane = tid & 31, wid = tid >> 5;

    const __half* Qg = Qf + ((size_t)(b * HQ_ + h) * T_ + qt * 128) * HD_;
    const __half* Kg = Kf + (size_t)(b * HK_ + hk) * T_ * HD_;
    const __half* Vg = Vf + (size_t)(b * HK_ + hk) * T_ * HD_;

    #pragma unroll
    for (int j = 0; j < 10; j++) {
        int c = tid + j * 256;
        int row = c / 20, col = (c % 20) * 8;
        cp16(smb + row * ROWB + col * 2, Qg + row * HD_ + col);
    }
    auto load_k = [&](int buf, int kt) {
        uint32_t base = smb + FKOFF + buf * FKV_SZ;
        const __half* s = Kg + (size_t)kt * 128 * HD_;
        #pragma unroll
        for (int j = 0; j < 10; j++) {
            int c = tid + j * 256;
            int row = c / 20, col = (c % 20) * 8;
            cp16(base + row * ROWB + col * 2, s + row * HD_ + col);
        }
    };
    auto load_v = [&](int buf, int kt) {
        uint32_t base = smb + FVOFF + buf * FKV_SZ;
        const __half* s = Vg + (size_t)kt * 128 * HD_;
        #pragma unroll
        for (int j = 0; j < 10; j++) {
            int c = tid + j * 256;
            int row = c / 20, col = (c % 20) * 8;
            cp16(base + row * ROWB + col * 2, s + row * HD_ + col);
        }
    };

    load_k(0, 0); CP_COMMIT();      // group: Q + K0
    load_v(0, 0); CP_COMMIT();      // group: V0

    float m0 = -1e30f, m1 = -1e30f, l0 = 0.f, l1 = 0.f;
    float o[20][4];
    #pragma unroll
    for (int f = 0; f < 20; f++)
        #pragma unroll
        for (int e = 0; e < 4; e++) o[f][e] = 0.f;

    const int gr = lane >> 2, ct = lane & 3;
    const int ldrow = (lane & 7) + ((lane >> 3) & 1) * 8;
    const int ldcol = ((lane >> 4) & 1) * 8;
    const uint32_t q_b = smb + (wid * 16 + ldrow) * ROWB + ldcol * 2;
    const int rowg0 = qt * 128 + wid * 16 + gr;

    const int nkt = qt + 1;
    const float sc = 0.07905694150420949f * 1.4426950408889634f;  // scale*log2e

    for (int kt = 0; kt < nkt; kt++) {
        if (kt + 1 < nkt) {
            load_k((kt + 1) & 1, kt + 1); CP_COMMIT();
            load_v((kt + 1) & 1, kt + 1); CP_COMMIT();
            CP_WAIT2();
        } else {
            CP_WAIT0();
        }
        __syncthreads();

        // ---- S = Q K^T (128 kv cols: 16 n8-fragments) ----
        float s[16][4];
        #pragma unroll
        for (int f = 0; f < 16; f++)
            #pragma unroll
            for (int e = 0; e < 4; e++) s[f][e] = 0.f;

        uint32_t kb = smb + FKOFF + (kt & 1) * FKV_SZ + ldrow * ROWB + ldcol * 2;
        #pragma unroll
        for (int ks = 0; ks < 10; ks++) {
            uint32_t a[4];
            ldm4(a, q_b + ks * 32);
            #pragma unroll
            for (int ng = 0; ng < 8; ng++) {
                uint32_t r[4];
                ldm4(r, kb + ng * 16 * ROWB + ks * 32);
                uint32_t b0[2] = {r[0], r[2]}, b1[2] = {r[1], r[3]};
                mma_f16(s[2 * ng], a, b0);
                mma_f16(s[2 * ng + 1], a, b1);
            }
        }

        // ---- mask + scale (base-2 domain) ----
        if (kt == nkt - 1) {     // diagonal tile
            #pragma unroll
            for (int f = 0; f < 16; f++) {
                int col = kt * 128 + f * 8 + 2 * ct;
                s[f][0] = (col     > rowg0)     ? -1e30f : s[f][0] * sc;
                s[f][1] = (col + 1 > rowg0)     ? -1e30f : s[f][1] * sc;
                s[f][2] = (col     > rowg0 + 8) ? -1e30f : s[f][2] * sc;
                s[f][3] = (col + 1 > rowg0 + 8) ? -1e30f : s[f][3] * sc;
            }
        } else {
            #pragma unroll
            for (int f = 0; f < 16; f++)
                #pragma unroll
                for (int e = 0; e < 4; e++) s[f][e] *= sc;
        }

        // ---- online softmax (max reduced across quad; l kept per-thread) ----
        float r0 = -1e30f, r1 = -1e30f;
        #pragma unroll
        for (int f = 0; f < 16; f++) {
            r0 = fmaxf(r0, fmaxf(s[f][0], s[f][1]));
            r1 = fmaxf(r1, fmaxf(s[f][2], s[f][3]));
        }
        r0 = fmaxf(r0, __shfl_xor_sync(0xffffffffu, r0, 1));
        r0 = fmaxf(r0, __shfl_xor_sync(0xffffffffu, r0, 2));
        r1 = fmaxf(r1, __shfl_xor_sync(0xffffffffu, r1, 1));
        r1 = fmaxf(r1, __shfl_xor_sync(0xffffffffu, r1, 2));
        float mn0 = fmaxf(m0, r0), mn1 = fmaxf(m1, r1);
        float a0 = exp2p(m0 - mn0), a1 = exp2p(m1 - mn1);
        m0 = mn0; m1 = mn1;

        float rs0 = 0.f, rs1 = 0.f;
        uint32_t pA[16], pB[16];
        #pragma unroll
        for (int f = 0; f < 16; f++) {
            float p0 = exp2p(s[f][0] - mn0);
            float p1 = exp2p(s[f][1] - mn0);
            float p2 = exp2p(s[f][2] - mn1);
            float p3 = exp2p(s[f][3] - mn1);
            rs0 += p0 + p1; rs1 += p2 + p3;
            __half2 hA = __floats2half2_rn(p0, p1);
            __half2 hB = __floats2half2_rn(p2, p3);
            pA[f] = *(uint32_t*)&hA;
            pB[f] = *(uint32_t*)&hB;
        }
        l0 = l0 * a0 + rs0;
        l1 = l1 * a1 + rs1;
        #pragma unroll
        for (int f = 0; f < 20; f++) {
            o[f][0] *= a0; o[f][1] *= a0; o[f][2] *= a1; o[f][3] *= a1;
        }

        // ---- O += P V (128 kv rows: 8 k16 chunks) ----
        uint32_t vbase = smb + FVOFF + (kt & 1) * FKV_SZ;
        #pragma unroll
        for (int ks = 0; ks < 8; ks++) {
            uint32_t a[4] = {pA[2 * ks], pB[2 * ks], pA[2 * ks + 1], pB[2 * ks + 1]};
            uint32_t vb = vbase + (ks * 16 + ldrow) * ROWB + ldcol * 2;
            #pragma unroll
            for (int nb = 0; nb < 10; nb++) {
                uint32_t r[4];
                ldm4t(r, vb + nb * 32);
                uint32_t b0[2] = {r[0], r[1]}, b1[2] = {r[2], r[3]};
                mma_f16(o[2 * nb], a, b0);
                mma_f16(o[2 * nb + 1], a, b1);
            }
        }
        __syncthreads();
    }

    // ---- epilogue: one l reduction, normalize, write fp16 [tok][D] ----
    l0 += __shfl_xor_sync(0xffffffffu, l0, 1);
    l0 += __shfl_xor_sync(0xffffffffu, l0, 2);
    l1 += __shfl_xor_sync(0xffffffffu, l1, 1);
    l1 += __shfl_xor_sync(0xffffffffu, l1, 2);
    float i0 = 1.f / l0, i1 = 1.f / l1;
    size_t rb0 = (size_t)(b * T_ + qt * 128 + wid * 16 + gr) * D_ + h * HD_;
    size_t rb1 = rb0 + 8 * (size_t)D_;
    #pragma unroll
    for (int f = 0; f < 20; f++) {
        int col = f * 8 + 2 * ct;
        __half2 h01 = __floats2half2_rn(o[f][0] * i0, o[f][1] * i0);
        __half2 h23 = __floats2half2_rn(o[f][2] * i1, o[f][3] * i1);
        *(uint32_t*)(Of + rb0 + col) = *(uint32_t*)&h01;
        *(uint32_t*)(Of + rb1 + col) = *(uint32_t*)&h23;
    }
}

// ---------------------------------------------------------------------------
// Host launch (serial, R15-proven order; merged head prep)
// ---------------------------------------------------------------------------
extern "C" void kernel_launch(void* const* d_in, const int* in_sizes, int n_in,
                              void* d_out, int out_size) {
    const float* x      = (const float*)d_in[0];
    const float* wq     = (const float*)d_in[1];
    const float* wk     = (const float*)d_in[2];
    const float* wv     = (const float*)d_in[3];
    const float* wo     = (const float*)d_in[4];
    const float* norm_w = (const float*)d_in[5];
    const float* norm_b = (const float*)d_in[6];
    const float* qn_w   = (const float*)d_in[7];
    const float* kn_w   = (const float*)d_in[8];
    float* out = (float*)d_out;

    __half *af, *wtf, *wof, *of, *qf, *kf, *vf, *qkv;
    float *tcos, *tsin;
    cudaGetSymbolAddress((void**)&af,   g_af);
    cudaGetSymbolAddress((void**)&wtf,  g_wtf);
    cudaGetSymbolAddress((void**)&wof,  g_wof);
    cudaGetSymbolAddress((void**)&of,   g_of);
    cudaGetSymbolAddress((void**)&qf,   g_qf);
    cudaGetSymbolAddress((void**)&kf,   g_kf);
    cudaGetSymbolAddress((void**)&vf,   g_vf);
    cudaGetSymbolAddress((void**)&qkv,  g_qkv);
    cudaGetSymbolAddress((void**)&tcos, g_cos);
    cudaGetSymbolAddress((void**)&tsin, g_sin);

    cudaFuncSetAttribute(hgemm<__half>, cudaFuncAttributeMaxDynamicSharedMemorySize, GEMM_SMEM);
    cudaFuncSetAttribute(hgemm<float>,  cudaFuncAttributeMaxDynamicSharedMemorySize, GEMM_SMEM);
    cudaFuncSetAttribute(flash_hmma, cudaFuncAttributeMaxDynamicSharedMemorySize, FLASH_SMEM);

    // 0. fused weight transpose [wq|wk|wv] -> fp16
    wsplit_h<<<dim3(NQKV / 32, D_ / 32), 256>>>(wq, wk, wv, wtf);
    // 1. RMS layernorm -> fp16 (single pass)
    rmsnorm_kernel<<<NTOK, 256>>>(x, norm_w, norm_b, af);
    // 2. rope tables
    rope_table_kernel<<<(T_ * RD_ + 255) / 256, 256>>>(tcos, tsin);
    // 3. fused QKV projection (fp16 HMMA, fp16 output)
    hgemm<__half><<<dim3(NQKV / BN, NTOK / BM), 256, GEMM_SMEM>>>(af, wtf, qkv, D_, NQKV);
    // 4. wo transpose -> fp16
    wsplit_h<<<dim3(D_ / 32, D_ / 32), 256>>>(wo, wo, wo, wof);
    // 5. merged head prep (q norm+rope, k norm+rope, v copy)
    head_prep_all<<<HP_BLKS, 256>>>(qkv, qn_w, kn_w, tcos, tsin, qf, kf, vf);
    // 6. fp16 HMMA flash attention (BKV=128, online softmax)
    flash_hmma<<<dim3(T_ / 128, HQ_, B_), 256, FLASH_SMEM>>>(qf, kf, vf, of);
    // 7. output projection (fp16 HMMA, fp32 output)
    hgemm<float><<<dim3(D_ / BN, NTOK / BM), 256, GEMM_SMEM>>>(of, wof, out, D_, D_);
}